// round 12
// baseline (speedup 1.0000x reference)
#include <cuda_runtime.h>
#include <math.h>

// ---------------------------------------------------------------------------
// Problem constants
// ---------------------------------------------------------------------------
#define BETA      10.0
#define LTAU      1000
#define N_NODES   256
#define N_IWN     256
#define BATCH     16
#define N_POLES   16

#define STEP_D    (9.99 / 999.0)            // linspace(0, BETA-DTAU, LTAU) step
#define LOG2E_F   1.4426950408889634f
#define PI_D      3.141592653589793
#define ZETA3     1.2020569031595942
#define ZETA5     1.0369277551433699
#define PG_CLAMP  1.3e36f                   // ~2^120 magnitude clamp for pg*rho^j

// Gauss-Legendre tables, computed on HOST (deterministic double Newton) each
// call and passed BY VALUE as kernel parameters -> baked into the graph node.
struct GLTab {
    float phi[N_NODES];
    float wgt[N_NODES];
};

// Per-(b,pole,node-quarter) partial G_tau: 1024 * 1000 floats = 4 MB (static).
__device__ float g_partial4[BATCH * N_POLES * 4 * LTAU];
// Per-batch completion tickets (zero-init; finisher resets to 0 every call).
__device__ int   g_cnt[BATCH];

__device__ __forceinline__ float fexp2(float x) {
    float y;
    asm("ex2.approx.ftz.f32 %0, %1;" : "=f"(y) : "f"(x));
    return y;
}

// ---- packed f32x2 helpers (Blackwell FFMA2 path, PTX-only) ----------------
__device__ __forceinline__ unsigned long long pk2(float lo, float hi) {
    unsigned long long r;
    asm("mov.b64 %0, {%1, %2};" : "=l"(r) : "f"(lo), "f"(hi));
    return r;
}
__device__ __forceinline__ void unpk2(float& lo, float& hi, unsigned long long v) {
    asm("mov.b64 {%0, %1}, %2;" : "=f"(lo), "=f"(hi) : "l"(v));
}
__device__ __forceinline__ unsigned long long fma2(unsigned long long a,
                                                   unsigned long long b,
                                                   unsigned long long c) {
    unsigned long long d;
    asm("fma.rn.f32x2 %0, %1, %2, %3;" : "=l"(d) : "l"(a), "l"(b), "l"(c));
    return d;
}

// ---------------------------------------------------------------------------
// Fused kernel.  Block = (bp, node-quarter q); 128 threads; grid 1024
// (~7 blocks/SM -> enough warps to hide the LDS/EX2 chains, unlike R8's 256).
//
// Phase 1 (quad): threads 0..63 precompute one node each:
//   E0(n, tau0) = 2^( q2*tau0 + d2 ),  q2 = -omega*log2e,
//   d2 = BETA*min(omega,0)*log2e,
//   pg = 0.5*(a - b*phi) * w / (1 + exp(-BETA*|omega|))
//   pg_j = pg * rho^j  (rho = 2^(q2*dtau), per-step magnitude-clamped)
// term(n, tau0 + j*dtau) = pg_j * E0 -> all 8 tau-accumulators share ONE
// exponential: inner body = 2 EX2 + 8 FFMA2 + 5 LDS.128 per packed pair.
// Threads 0..124 each cover 8 consecutive taus; partials -> g_partial4.
//
// Phase 2 (finisher): threadfence + per-batch ticket over the batch's 64
// blocks; the 64th block sums the 64 chunks (fixed order -> deterministic,
// L2-resident coalesced float4 loads), computes the Matsubara-tail G0,
// writes out[b][0], and resets the ticket.
//   Re(res/(z-i*nu)) = (a*eps - b*(gam+nu)) / (eps^2 + (gam+nu)^2)
//   Re(c1)/iwn correction is purely imaginary -> drops
//   corrections: +Re(c2)/nu^2 + Im(c3)/nu^3 - Re(c4)/nu^4 - Im(c5)/nu^5
// ---------------------------------------------------------------------------
__global__ void __launch_bounds__(128) fused_kernel(
    const GLTab tab,
    const float* __restrict__ pre, const float* __restrict__ pim,
    const float* __restrict__ rre, const float* __restrict__ rim,
    float* __restrict__ out)
{
    __shared__ float4     sh_qd[32];      // {q2_a,d2_a,q2_b,d2_b} per pair
    __shared__ ulonglong2 sh_pg[32][4];   // pg_j packed, 4 j-pairs per pair
    __shared__ int        s_ticket;
    __shared__ double     red[128];

    const int bp = blockIdx.x >> 2;       // b*16 + p
    const int q  = blockIdx.x & 3;        // node quarter
    const int b  = bp >> 4;
    const int t  = threadIdx.x;

    // ---- precompute: one node per thread (threads 0..63) ----
    if (t < 64) {
        const int n = q * 64 + t;
        float eps = pre[bp];
        float gam = -pim[bp];
        float a   = rre[bp];
        float br  = rim[bp];
        float phi = tab.phi[n];
        float wq  = tab.wgt[n];

        float omega = fmaf(gam, phi, eps);
        float s     = fabsf(omega);
        float q2 = -omega * LOG2E_F;
        float d2 = 10.0f * fminf(omega, 0.0f) * LOG2E_F;
        float gfac = 1.0f / (1.0f + fexp2(-10.0f * LOG2E_F * s));
        float pg = 0.5f * fmaf(-br, phi, a) * wq * gfac;
        float rho = fexp2(fminf(q2 * (float)STEP_D, 80.0f));

        float pj[8];
        pj[0] = pg;
        #pragma unroll
        for (int j = 1; j < 8; ++j) {
            float v = pj[j - 1] * rho;
            // magnitude clamp avoids inf; whenever active, the matching
            // E0 has flushed (or the true term is <= ~4e-5) -> safe
            pj[j] = copysignf(fminf(fabsf(v), PG_CLAMP), v);
        }

        const int pr = t >> 1, k = t & 1;         // pair index / half
        float* qd = (float*)&sh_qd[pr];
        qd[2 * k]     = q2;
        qd[2 * k + 1] = d2;
        #pragma unroll
        for (int jp = 0; jp < 4; ++jp) {          // pack pg_j lo/hi halves
            float* pp = (float*)&sh_pg[pr][jp];
            pp[k]     = pj[2 * jp];
            pp[2 + k] = pj[2 * jp + 1];
        }
    }
    __syncthreads();

    // ---- main quadrature loop: 8 taus per thread, shared E0 ----
    if (t < 125) {
        const int l0 = 8 * t;
        const float tau0 = (float)((double)l0 * STEP_D);

        unsigned long long A0 = 0, A1 = 0, A2 = 0, A3 = 0,
                           A4 = 0, A5 = 0, A6 = 0, A7 = 0;
        #pragma unroll 4
        for (int p = 0; p < 32; ++p) {
            float4 qd = sh_qd[p];                 // broadcast LDS.128
            float e0 = fexp2(fmaf(qd.x, tau0, qd.y));
            float e1 = fexp2(fmaf(qd.z, tau0, qd.w));
            unsigned long long E = pk2(e0, e1);
            ulonglong2 p01 = sh_pg[p][0];
            ulonglong2 p23 = sh_pg[p][1];
            ulonglong2 p45 = sh_pg[p][2];
            ulonglong2 p67 = sh_pg[p][3];
            A0 = fma2(p01.x, E, A0);
            A1 = fma2(p01.y, E, A1);
            A2 = fma2(p23.x, E, A2);
            A3 = fma2(p23.y, E, A3);
            A4 = fma2(p45.x, E, A4);
            A5 = fma2(p45.y, E, A5);
            A6 = fma2(p67.x, E, A6);
            A7 = fma2(p67.y, E, A7);
        }

        float lo, hi, r0, r1, r2, r3, r4, r5, r6, r7;
        unpk2(lo, hi, A0); r0 = lo + hi;
        unpk2(lo, hi, A1); r1 = lo + hi;
        unpk2(lo, hi, A2); r2 = lo + hi;
        unpk2(lo, hi, A3); r3 = lo + hi;
        unpk2(lo, hi, A4); r4 = lo + hi;
        unpk2(lo, hi, A5); r5 = lo + hi;
        unpk2(lo, hi, A6); r6 = lo + hi;
        unpk2(lo, hi, A7); r7 = lo + hi;

        float4* dst = (float4*)&g_partial4[(size_t)blockIdx.x * LTAU];
        dst[2 * t]     = make_float4(r0, r1, r2, r3);
        dst[2 * t + 1] = make_float4(r4, r5, r6, r7);
    }

    // ---- ticket: release stores, claim a ticket for this batch ----
    __threadfence();                     // order partial stores ...
    __syncthreads();                     // ... before thread 0's atomic
    if (t == 0) {
        int tk = atomicAdd(&g_cnt[b], 1);
        s_ticket = tk;
        if (tk == 63) __threadfence();   // acquire side
    }
    __syncthreads();
    if (s_ticket != 63) return;

    // =====================  FINISHER (one block per batch)  ================
    // ---- reduce the batch's 64 chunks for every tau (fixed order) ----
    const float4* src = (const float4*)&g_partial4[(size_t)b * 64 * LTAU];
    #pragma unroll
    for (int rr = 0; rr < 2; ++rr) {
        const int g = t + rr * 128;      // float4 group (4 taus)
        if (g < 250) {
            // two independent accumulators for ILP; (sA+sB) order is fixed
            float4 sA = make_float4(0.f, 0.f, 0.f, 0.f);
            float4 sB = make_float4(0.f, 0.f, 0.f, 0.f);
            #pragma unroll 8
            for (int c = 0; c < 32; ++c) {
                float4 vA = src[(size_t)(2 * c)     * 250 + g];
                float4 vB = src[(size_t)(2 * c + 1) * 250 + g];
                sA.x += vA.x; sA.y += vA.y; sA.z += vA.z; sA.w += vA.w;
                sB.x += vB.x; sB.y += vB.y; sB.z += vB.z; sB.w += vB.w;
            }
            float4 s;
            s.x = sA.x + sB.x; s.y = sA.y + sB.y;
            s.z = sA.z + sB.z; s.w = sA.w + sB.w;
            *(float4*)(out + (size_t)b * LTAU + 4 * g) = s;
        }
    }

    // ---- G0 (Matsubara tail): thread t handles frequencies t and t+128 ----
    const float nu1 = (2.0f * (float)t + 1.0f) * (float)(PI_D / 10.0);
    const float nu2_ = (2.0f * (float)(t + 128) + 1.0f) * (float)(PI_D / 10.0);
    float F1 = 0.f, F2 = 0.f, s1 = 0.f, s2 = 0.f, s3 = 0.f, s4 = 0.f, s5 = 0.f;

    #pragma unroll
    for (int p = 0; p < N_POLES; ++p) {
        float eps = pre[b * N_POLES + p];
        float gam = -pim[b * N_POLES + p];
        float a   = rre[b * N_POLES + p];
        float bb  = rim[b * N_POLES + p];

        float D1 = gam + nu1;
        F1 += (a * eps - bb * D1) / fmaf(eps, eps, D1 * D1);
        float D2 = gam + nu2_;
        F2 += (a * eps - bb * D2) / fmaf(eps, eps, D2 * D2);

        // c-chain: c1 = -res ; c_{k+1} = c_k * z, z = eps - i*gam
        float zr = eps, zi = -gam;
        float cr = -a, ci = -bb;
        s1 += cr;
        float r2 = cr * zr - ci * zi, i2 = cr * zi + ci * zr;  s2 += r2;
        float r3 = r2 * zr - i2 * zi, i3 = r2 * zi + i2 * zr;  s3 += i3;
        float r4 = r3 * zr - i3 * zi, i4 = r3 * zi + i3 * zr;  s4 += r4;
        float r5 = r4 * zr - i4 * zi, i5 = r4 * zi + i4 * zr;  s5 += i5;
    }
    {
        float n2 = nu1 * nu1, n3 = n2 * nu1;
        F1 += s2 / n2 + s3 / n3 - s4 / (n2 * n2) - s5 / (n2 * n3);
        float m2 = nu2_ * nu2_, m3 = m2 * nu2_;
        F2 += s2 / m2 + s3 / m3 - s4 / (m2 * m2) - s5 / (m2 * m3);
    }

    red[t] = (double)F1 + (double)F2;
    __syncthreads();
    for (int off = 64; off > 0; off >>= 1) {
        if (t < off) red[t] += red[t + off];
        __syncthreads();
    }

    if (t == 0) {
        const double C0 = -0.5;
        const double C1 = -BETA / 4.0;
        const double C2 = -7.0 * ZETA3 * BETA * BETA / (4.0 * PI_D * PI_D * PI_D);
        const double C3 = BETA * BETA * BETA / 48.0;
        const double C4 = 31.0 * ZETA5 * BETA * BETA * BETA * BETA /
                          (16.0 * PI_D * PI_D * PI_D * PI_D * PI_D);
        double G0 = C0 * (double)s1 + C1 * (double)s2 + C2 * (double)s3 +
                    C3 * (double)s4 + C4 * (double)s5 +
                    2.0 * red[0] / BETA;
        out[(size_t)b * LTAU] = (float)G0;   // overwrites l=0 (same thread
                                             // wrote it in the reduce: ordered)
        atomicExch(&g_cnt[b], 0);            // reset for next graph replay
    }
}

// ---------------------------------------------------------------------------
// Host: Gauss-Legendre nodes/weights (double Newton, fixed iteration count ->
// deterministic).  Runs at capture/correctness time only; values are baked
// into the graph as kernel parameters.  No device allocation, no stream ops.
// ---------------------------------------------------------------------------
static void host_leggauss(GLTab* tab)
{
    const int n = N_NODES;
    for (int i = 0; i < n; ++i) {
        double z = cos(PI_D * ((double)i + 0.75) / ((double)n + 0.5));
        double pp = 1.0;
        for (int it = 0; it < 6; ++it) {          // fixed count: deterministic
            double p1 = z, p2 = 1.0;
            for (int j = 1; j < n; ++j) {
                double p0 = ((2.0 * j + 1.0) * z * p1 - (double)j * p2)
                            / ((double)j + 1.0);
                p2 = p1; p1 = p0;
            }
            pp = (double)n * (z * p1 - p2) / (z * z - 1.0);
            z -= p1 / pp;
        }
        tab->phi[i] = (float)tan(1.5707963267948966 * z);
        tab->wgt[i] = (float)(2.0 / ((1.0 - z * z) * pp * pp));
    }
}

// ---------------------------------------------------------------------------
// Launch
// ---------------------------------------------------------------------------
extern "C" void kernel_launch(void* const* d_in, const int* in_sizes, int n_in,
                              void* d_out, int out_size)
{
    const float* pre = (const float*)d_in[0];  // poles_re    [16,16]
    const float* pim = (const float*)d_in[1];  // poles_im    [16,16]
    const float* rre = (const float*)d_in[2];  // residues_re [16,16]
    const float* rim = (const float*)d_in[3];  // residues_im [16,16]
    float* out = (float*)d_out;                // [16,1000] float32

    GLTab tab;                                 // recomputed every call (no caching)
    host_leggauss(&tab);

    fused_kernel<<<BATCH * N_POLES * 4, 128>>>(tab, pre, pim, rre, rim, out);
}

// round 13
// speedup vs baseline: 1.0880x; 1.0880x over previous
#include <cuda_runtime.h>
#include <math.h>

// ---------------------------------------------------------------------------
// Problem constants
// ---------------------------------------------------------------------------
#define BETA      10.0
#define LTAU      1000
#define N_NODES   256
#define N_IWN     256
#define BATCH     16
#define N_POLES   16

#define STEP_D    (9.99 / 999.0)            // linspace(0, BETA-DTAU, LTAU) step
#define LOG2E_F   1.4426950408889634f
#define PI_D      3.141592653589793
#define ZETA3     1.2020569031595942
#define ZETA5     1.0369277551433699

// Gauss-Legendre tables, computed on HOST (deterministic double Newton) each
// call and passed BY VALUE as kernel parameters -> baked into the graph node.
struct GLTab {
    float phi[N_NODES];
    float wgt[N_NODES];
};

// TRANSPOSED partials: partialT[b][g][c], g = float4 tau-group (250 per
// batch), c = chunk (pole*4 + node-quarter, 64 per batch).  4 MB static.
// Each reduce thread then reads 64 CONTIGUOUS float4 (1 KB).
__device__ float4 g_partialT[BATCH * 250 * 64];

__device__ __forceinline__ float fexp2(float x) {
    float y;
    asm("ex2.approx.ftz.f32 %0, %1;" : "=f"(y) : "f"(x));
    return y;
}

// ---- packed f32x2 helpers (Blackwell FFMA2 path, PTX-only) ----------------
__device__ __forceinline__ unsigned long long pk2(float lo, float hi) {
    unsigned long long r;
    asm("mov.b64 %0, {%1, %2};" : "=l"(r) : "f"(lo), "f"(hi));
    return r;
}
__device__ __forceinline__ void unpk2(float& lo, float& hi, unsigned long long v) {
    asm("mov.b64 {%0, %1}, %2;" : "=f"(lo), "=f"(hi) : "l"(v));
}
__device__ __forceinline__ unsigned long long fma2(unsigned long long a,
                                                   unsigned long long b,
                                                   unsigned long long c) {
    unsigned long long d;
    asm("fma.rn.f32x2 %0, %1, %2, %3;" : "=l"(d) : "l"(a), "l"(b), "l"(c));
    return d;
}
__device__ __forceinline__ unsigned long long mul2(unsigned long long a,
                                                   unsigned long long b) {
    unsigned long long d;
    asm("mul.rn.f32x2 %0, %1, %2;" : "=l"(d) : "l"(a), "l"(b));
    return d;
}

// ---------------------------------------------------------------------------
// Quadrature kernel (R7's proven 2-LDS / 17-op loop).  Block = (bp, node-
// quarter q); 128 threads; grid 1024.  Threads 0..63 precompute one node
// each into the packed pair layout; threads 0..124 each cover 8 consecutive
// taus via the geometric recurrence, node pairs packed into f32x2 lanes:
//   term(n,l) = pg * 2^( q2*tau_l + d2 ),   e_{l+1} = e_l * rho
//   q2 = -omega*log2e,  d2 = BETA*min(omega,0)*log2e
//   pg = 0.5*(a - b*phi) * w / (1 + exp(-BETA*|omega|))
// Inner body: 2 LDS.128 (32B) + 2 EX2 + 8 FFMA2 + 7 MUL2 -> fma-pipe-bound
// (the R9/R12 "shared-E0" variant was LDS-bound at 80B/iter: reverted).
// Results stored TRANSPOSED: partialT[b][g][c] so the reduce is contiguous.
// ---------------------------------------------------------------------------
__global__ void __launch_bounds__(128) quad_kernel(
    const GLTab tab,
    const float* __restrict__ pre, const float* __restrict__ pim,
    const float* __restrict__ rre, const float* __restrict__ rim)
{
    __shared__ float4     sh_qd[32];   // {q2_a, d2_a, q2_b, d2_b} per pair
    __shared__ ulonglong2 sh_pr[32];   // {pg packed, rho packed}  per pair
    const int bp = blockIdx.x >> 2;    // b*16 + p
    const int q  = blockIdx.x & 3;     // node quarter
    const int b  = bp >> 4;
    const int c  = (bp & 15) * 4 + q;  // chunk index within batch, 0..63
    const int t  = threadIdx.x;

    if (t < 64) {                      // per-node precompute (1 node / thread)
        const int n = q * 64 + t;
        float eps = pre[bp];
        float gam = -pim[bp];
        float a   = rre[bp];
        float br  = rim[bp];
        float phi = tab.phi[n];
        float wq  = tab.wgt[n];

        float omega = fmaf(gam, phi, eps);
        float s     = fabsf(omega);
        float q2 = -omega * LOG2E_F;
        float d2 = 10.0f * fminf(omega, 0.0f) * LOG2E_F;
        float gfac = 1.0f / (1.0f + fexp2(-10.0f * LOG2E_F * s));
        float pg = 0.5f * fmaf(-br, phi, a) * wq * gfac;
        // clamp keeps rho finite; when active, the thread's starting
        // exponential has already flushed to 0 -> no corruption possible
        float rho = fexp2(fminf(q2 * (float)STEP_D, 80.0f));

        const int pr = t >> 1, k = t & 1;      // pair index / half
        float* qd = (float*)&sh_qd[pr];
        qd[2 * k]     = q2;
        qd[2 * k + 1] = d2;
        float* pp = (float*)&sh_pr[pr];
        pp[k]     = pg;                        // pg packed lo/hi
        pp[2 + k] = rho;                       // rho packed lo/hi
    }
    __syncthreads();

    if (t >= 125) return;              // 125 threads * 8 taus = 1000
    const int l0 = 8 * t;
    const float tau0 = (float)((double)l0 * STEP_D);

    unsigned long long A0 = 0, A1 = 0, A2 = 0, A3 = 0,
                       A4 = 0, A5 = 0, A6 = 0, A7 = 0;
    #pragma unroll 4
    for (int p = 0; p < 32; ++p) {
        float4     qd = sh_qd[p];       // broadcast LDS.128
        ulonglong2 pr = sh_pr[p];       // broadcast LDS.128
        float e0 = fexp2(fmaf(qd.x, tau0, qd.y));
        float e1 = fexp2(fmaf(qd.z, tau0, qd.w));
        unsigned long long E = pk2(e0, e1);
        A0 = fma2(pr.x, E, A0);  E = mul2(E, pr.y);
        A1 = fma2(pr.x, E, A1);  E = mul2(E, pr.y);
        A2 = fma2(pr.x, E, A2);  E = mul2(E, pr.y);
        A3 = fma2(pr.x, E, A3);  E = mul2(E, pr.y);
        A4 = fma2(pr.x, E, A4);  E = mul2(E, pr.y);
        A5 = fma2(pr.x, E, A5);  E = mul2(E, pr.y);
        A6 = fma2(pr.x, E, A6);  E = mul2(E, pr.y);
        A7 = fma2(pr.x, E, A7);
    }

    float lo, hi, r0, r1, r2, r3, r4, r5, r6, r7;
    unpk2(lo, hi, A0); r0 = lo + hi;
    unpk2(lo, hi, A1); r1 = lo + hi;
    unpk2(lo, hi, A2); r2 = lo + hi;
    unpk2(lo, hi, A3); r3 = lo + hi;
    unpk2(lo, hi, A4); r4 = lo + hi;
    unpk2(lo, hi, A5); r5 = lo + hi;
    unpk2(lo, hi, A6); r6 = lo + hi;
    unpk2(lo, hi, A7); r7 = lo + hi;

    // transposed scatter: two STG.128, stride 1 KB between adjacent threads
    const size_t base = ((size_t)b * 250 + 2 * t) * 64 + c;
    g_partialT[base]      = make_float4(r0, r1, r2, r3);
    g_partialT[base + 64] = make_float4(r4, r5, r6, r7);
}

// ---------------------------------------------------------------------------
// Reduce + G0 kernel (grid 32 x 256).
//  Blocks 0..15 : thread = one (b, g) tau-group; reads its 64 CONTIGUOUS
//    float4 chunk partials (1 KB), sums in fixed 4-lane-interleaved order
//    (deterministic), writes out[b][4g..4g+3].  Skips out[b][0].
//  Blocks 16..31: Matsubara tail -> out[b][0]   (independent)
//   Re(res/(z-i*nu)) = (a*eps - b*(gam+nu)) / (eps^2 + (gam+nu)^2)
//   Re(c1)/iwn correction is purely imaginary -> drops
//   corrections: +Re(c2)/nu^2 + Im(c3)/nu^3 - Re(c4)/nu^4 - Im(c5)/nu^5
// ---------------------------------------------------------------------------
__global__ void __launch_bounds__(256) reduce_g0_kernel(
    const float* __restrict__ pre, const float* __restrict__ pim,
    const float* __restrict__ rre, const float* __restrict__ rim,
    float* __restrict__ out)
{
    const int t = threadIdx.x;

    if (blockIdx.x < 16) {
        const int idx = blockIdx.x * 256 + t;    // (b,g) pairs: 16*250 = 4000
        if (idx >= 4000) return;
        const int b = idx / 250;
        const int g = idx - 250 * b;

        const float4* __restrict__ src = &g_partialT[(size_t)idx * 64];
        float4 s0 = make_float4(0.f, 0.f, 0.f, 0.f);
        float4 s1 = s0, s2 = s0, s3 = s0;
        #pragma unroll
        for (int k = 0; k < 16; ++k) {           // 16 rounds x 4 indep loads
            float4 v0 = src[4 * k];
            float4 v1 = src[4 * k + 1];
            float4 v2 = src[4 * k + 2];
            float4 v3 = src[4 * k + 3];
            s0.x += v0.x; s0.y += v0.y; s0.z += v0.z; s0.w += v0.w;
            s1.x += v1.x; s1.y += v1.y; s1.z += v1.z; s1.w += v1.w;
            s2.x += v2.x; s2.y += v2.y; s2.z += v2.z; s2.w += v2.w;
            s3.x += v3.x; s3.y += v3.y; s3.z += v3.z; s3.w += v3.w;
        }
        float4 s;
        s.x = (s0.x + s1.x) + (s2.x + s3.x);
        s.y = (s0.y + s1.y) + (s2.y + s3.y);
        s.z = (s0.z + s1.z) + (s2.z + s3.z);
        s.w = (s0.w + s1.w) + (s2.w + s3.w);

        float* dst = out + (size_t)b * LTAU + 4 * g;
        if (g == 0) { dst[1] = s.y; dst[2] = s.z; dst[3] = s.w; }
        else        { *(float4*)dst = s; }
        return;
    }

    // ---- G0 (Matsubara tail), thread t = frequency t ----
    __shared__ double red[256];
    const int b = blockIdx.x - 16;
    const float nu = (2.0f * (float)t + 1.0f) * (float)(PI_D / 10.0);
    float Ff = 0.f, s1 = 0.f, s2 = 0.f, s3 = 0.f, s4 = 0.f, s5 = 0.f;

    #pragma unroll
    for (int p = 0; p < N_POLES; ++p) {
        float eps = pre[b * N_POLES + p];
        float gam = -pim[b * N_POLES + p];
        float a   = rre[b * N_POLES + p];
        float bb  = rim[b * N_POLES + p];

        float D = gam + nu;
        Ff += (a * eps - bb * D) / fmaf(eps, eps, D * D);

        // c-chain: c1 = -res ; c_{k+1} = c_k * z, z = eps - i*gam
        float zr = eps, zi = -gam;
        float cr = -a, ci = -bb;
        s1 += cr;
        float r2 = cr * zr - ci * zi, i2 = cr * zi + ci * zr;  s2 += r2;
        float r3 = r2 * zr - i2 * zi, i3 = r2 * zi + i2 * zr;  s3 += i3;
        float r4 = r3 * zr - i3 * zi, i4 = r3 * zi + i3 * zr;  s4 += r4;
        float r5 = r4 * zr - i4 * zi, i5 = r4 * zi + i4 * zr;  s5 += i5;
    }
    float nu2 = nu * nu;
    float nu3 = nu2 * nu;
    Ff += s2 / nu2 + s3 / nu3 - s4 / (nu2 * nu2) - s5 / (nu2 * nu3);

    red[t] = (double)Ff;
    __syncthreads();
    for (int off = 128; off > 0; off >>= 1) {
        if (t < off) red[t] += red[t + off];
        __syncthreads();
    }

    if (t == 0) {
        const double C0 = -0.5;
        const double C1 = -BETA / 4.0;
        const double C2 = -7.0 * ZETA3 * BETA * BETA / (4.0 * PI_D * PI_D * PI_D);
        const double C3 = BETA * BETA * BETA / 48.0;
        const double C4 = 31.0 * ZETA5 * BETA * BETA * BETA * BETA /
                          (16.0 * PI_D * PI_D * PI_D * PI_D * PI_D);
        double G0 = C0 * (double)s1 + C1 * (double)s2 + C2 * (double)s3 +
                    C3 * (double)s4 + C4 * (double)s5 +
                    2.0 * red[0] / BETA;
        out[(size_t)b * LTAU] = (float)G0;
    }
}

// ---------------------------------------------------------------------------
// Host: Gauss-Legendre nodes/weights (double Newton, fixed iteration count ->
// deterministic).  Runs at capture/correctness time only; values are baked
// into the graph as kernel parameters.  No device allocation, no stream ops.
// ---------------------------------------------------------------------------
static void host_leggauss(GLTab* tab)
{
    const int n = N_NODES;
    for (int i = 0; i < n; ++i) {
        double z = cos(PI_D * ((double)i + 0.75) / ((double)n + 0.5));
        double pp = 1.0;
        for (int it = 0; it < 6; ++it) {          // fixed count: deterministic
            double p1 = z, p2 = 1.0;
            for (int j = 1; j < n; ++j) {
                double p0 = ((2.0 * j + 1.0) * z * p1 - (double)j * p2)
                            / ((double)j + 1.0);
                p2 = p1; p1 = p0;
            }
            pp = (double)n * (z * p1 - p2) / (z * z - 1.0);
            z -= p1 / pp;
        }
        tab->phi[i] = (float)tan(1.5707963267948966 * z);
        tab->wgt[i] = (float)(2.0 / ((1.0 - z * z) * pp * pp));
    }
}

// ---------------------------------------------------------------------------
// Launch
// ---------------------------------------------------------------------------
extern "C" void kernel_launch(void* const* d_in, const int* in_sizes, int n_in,
                              void* d_out, int out_size)
{
    const float* pre = (const float*)d_in[0];  // poles_re    [16,16]
    const float* pim = (const float*)d_in[1];  // poles_im    [16,16]
    const float* rre = (const float*)d_in[2];  // residues_re [16,16]
    const float* rim = (const float*)d_in[3];  // residues_im [16,16]
    float* out = (float*)d_out;                // [16,1000] float32

    GLTab tab;                                 // recomputed every call (no caching)
    host_leggauss(&tab);

    quad_kernel<<<BATCH * N_POLES * 4, 128>>>(tab, pre, pim, rre, rim);
    reduce_g0_kernel<<<32, 256>>>(pre, pim, rre, rim, out);
}

// round 16
// speedup vs baseline: 1.4981x; 1.3769x over previous
#include <cuda_runtime.h>
#include <math.h>

// ---------------------------------------------------------------------------
// Problem constants
// ---------------------------------------------------------------------------
#define BETA      10.0
#define LTAU      1000
#define N_NODES   256
#define N_IWN     256
#define BATCH     16
#define N_POLES   16

#define STEP_D    (9.99 / 999.0)            // linspace(0, BETA-DTAU, LTAU) step
#define LOG2E_F   1.4426950408889634f
#define PI_D      3.141592653589793
#define ZETA3     1.2020569031595942
#define ZETA5     1.0369277551433699

// Gauss-Legendre tables, computed on HOST (deterministic double Newton) each
// call and passed BY VALUE as kernel parameters -> baked into the graph node.
struct GLTab {
    float phi[N_NODES];
    float wgt[N_NODES];
};

// TRANSPOSED partials: partialT[b][g][c], g = float4 tau-group (250 per
// batch), c = chunk (pole*4 + node-quarter, 64 per batch).  4 MB static.
__device__ float4 g_partialT[BATCH * 250 * 64];

__device__ __forceinline__ float fexp2(float x) {
    float y;
    asm("ex2.approx.ftz.f32 %0, %1;" : "=f"(y) : "f"(x));
    return y;
}

// ---- packed f32x2 helpers (Blackwell FFMA2 path, PTX-only) ----------------
__device__ __forceinline__ unsigned long long pk2(float lo, float hi) {
    unsigned long long r;
    asm("mov.b64 %0, {%1, %2};" : "=l"(r) : "f"(lo), "f"(hi));
    return r;
}
__device__ __forceinline__ void unpk2(float& lo, float& hi, unsigned long long v) {
    asm("mov.b64 {%0, %1}, %2;" : "=f"(lo), "=f"(hi) : "l"(v));
}
__device__ __forceinline__ unsigned long long fma2(unsigned long long a,
                                                   unsigned long long b,
                                                   unsigned long long c) {
    unsigned long long d;
    asm("fma.rn.f32x2 %0, %1, %2, %3;" : "=l"(d) : "l"(a), "l"(b), "l"(c));
    return d;
}
__device__ __forceinline__ unsigned long long mul2(unsigned long long a,
                                                   unsigned long long b) {
    unsigned long long d;
    asm("mul.rn.f32x2 %0, %1, %2;" : "=l"(d) : "l"(a), "l"(b));
    return d;
}

// ---------------------------------------------------------------------------
// Quadrature kernel (R13, unchanged).  Block = (bp, node-quarter q);
// 128 threads; grid 1024.  Threads 0..63 precompute one node each; threads
// 0..124 each cover 8 consecutive taus via the geometric recurrence, node
// pairs packed into f32x2 lanes:
//   term(n,l) = pg * 2^( q2*tau_l + d2 ),   e_{l+1} = e_l * rho
//   q2 = -omega*log2e,  d2 = BETA*min(omega,0)*log2e
//   pg = 0.5*(a - b*phi) * w / (1 + exp(-BETA*|omega|))
// Inner body: 2 LDS.128 (32B) + 2 EX2 + 8 FFMA2 + 7 MUL2 -> fma-pipe-bound.
// Results stored TRANSPOSED: partialT[b][g][c] so the reduce is contiguous.
// ---------------------------------------------------------------------------
__global__ void __launch_bounds__(128) quad_kernel(
    const GLTab tab,
    const float* __restrict__ pre, const float* __restrict__ pim,
    const float* __restrict__ rre, const float* __restrict__ rim)
{
    __shared__ float4     sh_qd[32];   // {q2_a, d2_a, q2_b, d2_b} per pair
    __shared__ ulonglong2 sh_pr[32];   // {pg packed, rho packed}  per pair
    const int bp = blockIdx.x >> 2;    // b*16 + p
    const int q  = blockIdx.x & 3;     // node quarter
    const int b  = bp >> 4;
    const int c  = (bp & 15) * 4 + q;  // chunk index within batch, 0..63
    const int t  = threadIdx.x;

    if (t < 64) {                      // per-node precompute (1 node / thread)
        const int n = q * 64 + t;
        float eps = pre[bp];
        float gam = -pim[bp];
        float a   = rre[bp];
        float br  = rim[bp];
        float phi = tab.phi[n];
        float wq  = tab.wgt[n];

        float omega = fmaf(gam, phi, eps);
        float s     = fabsf(omega);
        float q2 = -omega * LOG2E_F;
        float d2 = 10.0f * fminf(omega, 0.0f) * LOG2E_F;
        float gfac = 1.0f / (1.0f + fexp2(-10.0f * LOG2E_F * s));
        float pg = 0.5f * fmaf(-br, phi, a) * wq * gfac;
        // clamp keeps rho finite; when active, the thread's starting
        // exponential has already flushed to 0 -> no corruption possible
        float rho = fexp2(fminf(q2 * (float)STEP_D, 80.0f));

        const int pr = t >> 1, k = t & 1;      // pair index / half
        float* qd = (float*)&sh_qd[pr];
        qd[2 * k]     = q2;
        qd[2 * k + 1] = d2;
        float* pp = (float*)&sh_pr[pr];
        pp[k]     = pg;                        // pg packed lo/hi
        pp[2 + k] = rho;                       // rho packed lo/hi
    }
    __syncthreads();

    if (t >= 125) return;              // 125 threads * 8 taus = 1000
    const int l0 = 8 * t;
    const float tau0 = (float)((double)l0 * STEP_D);

    unsigned long long A0 = 0, A1 = 0, A2 = 0, A3 = 0,
                       A4 = 0, A5 = 0, A6 = 0, A7 = 0;
    #pragma unroll 4
    for (int p = 0; p < 32; ++p) {
        float4     qd = sh_qd[p];       // broadcast LDS.128
        ulonglong2 pr = sh_pr[p];       // broadcast LDS.128
        float e0 = fexp2(fmaf(qd.x, tau0, qd.y));
        float e1 = fexp2(fmaf(qd.z, tau0, qd.w));
        unsigned long long E = pk2(e0, e1);
        A0 = fma2(pr.x, E, A0);  E = mul2(E, pr.y);
        A1 = fma2(pr.x, E, A1);  E = mul2(E, pr.y);
        A2 = fma2(pr.x, E, A2);  E = mul2(E, pr.y);
        A3 = fma2(pr.x, E, A3);  E = mul2(E, pr.y);
        A4 = fma2(pr.x, E, A4);  E = mul2(E, pr.y);
        A5 = fma2(pr.x, E, A5);  E = mul2(E, pr.y);
        A6 = fma2(pr.x, E, A6);  E = mul2(E, pr.y);
        A7 = fma2(pr.x, E, A7);
    }

    float lo, hi, r0, r1, r2, r3, r4, r5, r6, r7;
    unpk2(lo, hi, A0); r0 = lo + hi;
    unpk2(lo, hi, A1); r1 = lo + hi;
    unpk2(lo, hi, A2); r2 = lo + hi;
    unpk2(lo, hi, A3); r3 = lo + hi;
    unpk2(lo, hi, A4); r4 = lo + hi;
    unpk2(lo, hi, A5); r5 = lo + hi;
    unpk2(lo, hi, A6); r6 = lo + hi;
    unpk2(lo, hi, A7); r7 = lo + hi;

    // transposed scatter: two STG.128, stride 1 KB between adjacent threads
    const size_t base = ((size_t)b * 250 + 2 * t) * 64 + c;
    g_partialT[base]      = make_float4(r0, r1, r2, r3);
    g_partialT[base + 64] = make_float4(r4, r5, r6, r7);
}

// ---------------------------------------------------------------------------
// Reduce + G0 kernel (grid 141 x 256).
//  Blocks 0..124 : 8 threads per (b,g) tau-group (32000 threads total).
//    Thread sub s sums chunks {k*8+s}: per warp-instruction the 32 lane
//    addresses form 4 contiguous 128B segments -> fully coalesced, 8
//    independent LDG.128 per thread, 125 SMs issuing -> BW/latency both OK
//    (R13's 16-SM version capped at 315 GB/s: SM count was the limiter).
//    3-round shfl_xor tree (fixed order -> deterministic); lane sub==0
//    stores out[b][4g..4g+3], skipping out[b][0].
//  Blocks 125..140: Matsubara tail -> out[b][0]   (independent)
//   Re(res/(z-i*nu)) = (a*eps - b*(gam+nu)) / (eps^2 + (gam+nu)^2)
//   Re(c1)/iwn correction is purely imaginary -> drops
//   corrections: +Re(c2)/nu^2 + Im(c3)/nu^3 - Re(c4)/nu^4 - Im(c5)/nu^5
// ---------------------------------------------------------------------------
__global__ void __launch_bounds__(256) reduce_g0_kernel(
    const float* __restrict__ pre, const float* __restrict__ pim,
    const float* __restrict__ rre, const float* __restrict__ rim,
    float* __restrict__ out)
{
    const int t = threadIdx.x;

    if (blockIdx.x < 125) {
        const int tid = blockIdx.x * 256 + t;    // 0..31999
        const int gid = tid >> 3;                // (b,g) group, 0..3999
        const int sub = tid & 7;                 // 8-way split of the 64 chunks
        const int b   = gid / 250;
        const int g   = gid - 250 * b;

        const float4* __restrict__ src = &g_partialT[(size_t)gid * 64];
        float4 s = make_float4(0.f, 0.f, 0.f, 0.f);
        #pragma unroll
        for (int k = 0; k < 8; ++k) {            // 8 independent coalesced loads
            float4 v = src[k * 8 + sub];
            s.x += v.x; s.y += v.y; s.z += v.z; s.w += v.w;
        }
        // 3-round butterfly; combine order fixed per lane -> deterministic
        #pragma unroll
        for (int m = 4; m > 0; m >>= 1) {
            s.x += __shfl_xor_sync(0xffffffffu, s.x, m);
            s.y += __shfl_xor_sync(0xffffffffu, s.y, m);
            s.z += __shfl_xor_sync(0xffffffffu, s.z, m);
            s.w += __shfl_xor_sync(0xffffffffu, s.w, m);
        }

        if (sub == 0) {
            float* dst = out + (size_t)b * LTAU + 4 * g;
            if (g == 0) { dst[1] = s.y; dst[2] = s.z; dst[3] = s.w; }
            else        { *(float4*)dst = s; }
        }
        return;
    }

    // ---- G0 (Matsubara tail), thread t = frequency t ----
    __shared__ double red[256];
    const int b = blockIdx.x - 125;
    const float nu = (2.0f * (float)t + 1.0f) * (float)(PI_D / 10.0);
    float Ff = 0.f, s1 = 0.f, s2 = 0.f, s3 = 0.f, s4 = 0.f, s5 = 0.f;

    #pragma unroll
    for (int p = 0; p < N_POLES; ++p) {
        float eps = pre[b * N_POLES + p];
        float gam = -pim[b * N_POLES + p];
        float a   = rre[b * N_POLES + p];
        float bb  = rim[b * N_POLES + p];

        float D = gam + nu;
        Ff += (a * eps - bb * D) / fmaf(eps, eps, D * D);

        // c-chain: c1 = -res ; c_{k+1} = c_k * z, z = eps - i*gam
        float zr = eps, zi = -gam;
        float cr = -a, ci = -bb;
        s1 += cr;
        float r2 = cr * zr - ci * zi, i2 = cr * zi + ci * zr;  s2 += r2;
        float r3 = r2 * zr - i2 * zi, i3 = r2 * zi + i2 * zr;  s3 += i3;
        float r4 = r3 * zr - i3 * zi, i4 = r3 * zi + i3 * zr;  s4 += r4;
        float r5 = r4 * zr - i4 * zi, i5 = r4 * zi + i4 * zr;  s5 += i5;
    }
    float nu2 = nu * nu;
    float nu3 = nu2 * nu;
    Ff += s2 / nu2 + s3 / nu3 - s4 / (nu2 * nu2) - s5 / (nu2 * nu3);

    red[t] = (double)Ff;
    __syncthreads();
    for (int off = 128; off > 0; off >>= 1) {
        if (t < off) red[t] += red[t + off];
        __syncthreads();
    }

    if (t == 0) {
        const double C0 = -0.5;
        const double C1 = -BETA / 4.0;
        const double C2 = -7.0 * ZETA3 * BETA * BETA / (4.0 * PI_D * PI_D * PI_D);
        const double C3 = BETA * BETA * BETA / 48.0;
        const double C4 = 31.0 * ZETA5 * BETA * BETA * BETA * BETA /
                          (16.0 * PI_D * PI_D * PI_D * PI_D * PI_D);
        double G0 = C0 * (double)s1 + C1 * (double)s2 + C2 * (double)s3 +
                    C3 * (double)s4 + C4 * (double)s5 +
                    2.0 * red[0] / BETA;
        out[(size_t)b * LTAU] = (float)G0;
    }
}

// ---------------------------------------------------------------------------
// Host: Gauss-Legendre nodes/weights (double Newton, fixed iteration count ->
// deterministic).  Runs at capture/correctness time only; values are baked
// into the graph as kernel parameters.  No device allocation, no stream ops.
// ---------------------------------------------------------------------------
static void host_leggauss(GLTab* tab)
{
    const int n = N_NODES;
    for (int i = 0; i < n; ++i) {
        double z = cos(PI_D * ((double)i + 0.75) / ((double)n + 0.5));
        double pp = 1.0;
        for (int it = 0; it < 6; ++it) {          // fixed count: deterministic
            double p1 = z, p2 = 1.0;
            for (int j = 1; j < n; ++j) {
                double p0 = ((2.0 * j + 1.0) * z * p1 - (double)j * p2)
                            / ((double)j + 1.0);
                p2 = p1; p1 = p0;
            }
            pp = (double)n * (z * p1 - p2) / (z * z - 1.0);
            z -= p1 / pp;
        }
        tab->phi[i] = (float)tan(1.5707963267948966 * z);
        tab->wgt[i] = (float)(2.0 / ((1.0 - z * z) * pp * pp));
    }
}

// ---------------------------------------------------------------------------
// Launch
// ---------------------------------------------------------------------------
extern "C" void kernel_launch(void* const* d_in, const int* in_sizes, int n_in,
                              void* d_out, int out_size)
{
    const float* pre = (const float*)d_in[0];  // poles_re    [16,16]
    const float* pim = (const float*)d_in[1];  // poles_im    [16,16]
    const float* rre = (const float*)d_in[2];  // residues_re [16,16]
    const float* rim = (const float*)d_in[3];  // residues_im [16,16]
    float* out = (float*)d_out;                // [16,1000] float32

    GLTab tab;                                 // recomputed every call (no caching)
    host_leggauss(&tab);

    quad_kernel<<<BATCH * N_POLES * 4, 128>>>(tab, pre, pim, rre, rim);
    reduce_g0_kernel<<<141, 256>>>(pre, pim, rre, rim, out);
}

// round 17
// speedup vs baseline: 1.6794x; 1.1210x over previous
#include <cuda_runtime.h>
#include <math.h>

// ---------------------------------------------------------------------------
// Problem constants
// ---------------------------------------------------------------------------
#define BETA      10.0
#define LTAU      1000
#define N_NODES   256
#define N_IWN     256
#define BATCH     16
#define N_POLES   16

#define STEP_D    (9.99 / 999.0)            // linspace(0, BETA-DTAU, LTAU) step
#define LOG2E_F   1.4426950408889634f
#define PI_D      3.141592653589793
#define ZETA3     1.2020569031595942
#define ZETA5     1.0369277551433699

// Gauss-Legendre tables, computed on HOST (deterministic double Newton) each
// call and passed BY VALUE as kernel parameters -> baked into the graph node.
struct GLTab {
    float phi[N_NODES];
    float wgt[N_NODES];
};

// TRANSPOSED partials: partialT[b][g][c], g = float4 tau-group (250 per
// batch), c = chunk (polepair*4 + quarter, 32 per batch).  2 MB static.
__device__ float4 g_partialT[BATCH * 250 * 32];

__device__ __forceinline__ float fexp2(float x) {
    float y;
    asm("ex2.approx.ftz.f32 %0, %1;" : "=f"(y) : "f"(x));
    return y;
}

// ---- packed f32x2 helpers (Blackwell FFMA2 path, PTX-only) ----------------
__device__ __forceinline__ unsigned long long pk2(float lo, float hi) {
    unsigned long long r;
    asm("mov.b64 %0, {%1, %2};" : "=l"(r) : "f"(lo), "f"(hi));
    return r;
}
__device__ __forceinline__ void unpk2(float& lo, float& hi, unsigned long long v) {
    asm("mov.b64 {%0, %1}, %2;" : "=f"(lo), "=f"(hi) : "l"(v));
}
__device__ __forceinline__ unsigned long long fma2(unsigned long long a,
                                                   unsigned long long b,
                                                   unsigned long long c) {
    unsigned long long d;
    asm("fma.rn.f32x2 %0, %1, %2, %3;" : "=l"(d) : "l"(a), "l"(b), "l"(c));
    return d;
}
__device__ __forceinline__ unsigned long long mul2(unsigned long long a,
                                                   unsigned long long b) {
    unsigned long long d;
    asm("mul.rn.f32x2 %0, %1, %2;" : "=l"(d) : "l"(a), "l"(b));
    return d;
}

// ---------------------------------------------------------------------------
// Quad + G0 kernel.
//  Blocks 0..511 = (b, pole-pair pp, quarter q); 128 threads.  All 128
//  threads precompute one node each (2 poles x 64 nodes) into 64 packed
//  pairs; threads 0..124 each cover 8 consecutive taus via the geometric
//  recurrence over all 64 pairs (both poles summed in-register):
//   term(n,l) = pg * 2^( q2*tau_l + d2 ),   e_{l+1} = e_l * rho
//   q2 = -omega*log2e,  d2 = BETA*min(omega,0)*log2e
//   pg = 0.5*(a - b*phi) * w / (1 + exp(-BETA*|omega|))
//  Inner body: 2 LDS.128 (32B) + 2 EX2 + 8 FFMA2 + 7 MUL2 -> fma-pipe-bound.
//  Partials stored TRANSPOSED: partialT[b][g][c], c = pp*4+q (32 chunks).
//  Blocks 512..527: Matsubara tail -> out[b][0]  (input-only: independent
//  of the partials, so it rides in this launch, off the reduce path).
//   Re(res/(z-i*nu)) = (a*eps - b*(gam+nu)) / (eps^2 + (gam+nu)^2)
//   Re(c1)/iwn correction is purely imaginary -> drops
//   corrections: +Re(c2)/nu^2 + Im(c3)/nu^3 - Re(c4)/nu^4 - Im(c5)/nu^5
// ---------------------------------------------------------------------------
__global__ void __launch_bounds__(128) quad_g0_kernel(
    const GLTab tab,
    const float* __restrict__ pre, const float* __restrict__ pim,
    const float* __restrict__ rre, const float* __restrict__ rim,
    float* __restrict__ out)
{
    const int t = threadIdx.x;

    if (blockIdx.x >= 512) {
        // ---- G0 (Matsubara tail): thread t = frequencies t and t+128 ----
        __shared__ double red[128];
        const int b = blockIdx.x - 512;
        const float nu1  = (2.0f * (float)t + 1.0f) * (float)(PI_D / 10.0);
        const float nu2_ = (2.0f * (float)(t + 128) + 1.0f) * (float)(PI_D / 10.0);
        float F1 = 0.f, F2 = 0.f, s1 = 0.f, s2 = 0.f, s3 = 0.f, s4 = 0.f, s5 = 0.f;

        #pragma unroll
        for (int p = 0; p < N_POLES; ++p) {
            float eps = pre[b * N_POLES + p];
            float gam = -pim[b * N_POLES + p];
            float a   = rre[b * N_POLES + p];
            float bb  = rim[b * N_POLES + p];

            float D1 = gam + nu1;
            F1 += (a * eps - bb * D1) / fmaf(eps, eps, D1 * D1);
            float D2 = gam + nu2_;
            F2 += (a * eps - bb * D2) / fmaf(eps, eps, D2 * D2);

            // c-chain: c1 = -res ; c_{k+1} = c_k * z, z = eps - i*gam
            float zr = eps, zi = -gam;
            float cr = -a, ci = -bb;
            s1 += cr;
            float r2 = cr * zr - ci * zi, i2 = cr * zi + ci * zr;  s2 += r2;
            float r3 = r2 * zr - i2 * zi, i3 = r2 * zi + i2 * zr;  s3 += i3;
            float r4 = r3 * zr - i3 * zi, i4 = r3 * zi + i3 * zr;  s4 += r4;
            float r5 = r4 * zr - i4 * zi, i5 = r4 * zi + i4 * zr;  s5 += i5;
        }
        {
            float n2 = nu1 * nu1, n3 = n2 * nu1;
            F1 += s2 / n2 + s3 / n3 - s4 / (n2 * n2) - s5 / (n2 * n3);
            float m2 = nu2_ * nu2_, m3 = m2 * nu2_;
            F2 += s2 / m2 + s3 / m3 - s4 / (m2 * m2) - s5 / (m2 * m3);
        }

        red[t] = (double)F1 + (double)F2;
        __syncthreads();
        for (int off = 64; off > 0; off >>= 1) {
            if (t < off) red[t] += red[t + off];
            __syncthreads();
        }

        if (t == 0) {
            const double C0 = -0.5;
            const double C1 = -BETA / 4.0;
            const double C2 = -7.0 * ZETA3 * BETA * BETA / (4.0 * PI_D * PI_D * PI_D);
            const double C3 = BETA * BETA * BETA / 48.0;
            const double C4 = 31.0 * ZETA5 * BETA * BETA * BETA * BETA /
                              (16.0 * PI_D * PI_D * PI_D * PI_D * PI_D);
            double G0 = C0 * (double)s1 + C1 * (double)s2 + C2 * (double)s3 +
                        C3 * (double)s4 + C4 * (double)s5 +
                        2.0 * red[0] / BETA;
            out[(size_t)b * LTAU] = (float)G0;
        }
        return;
    }

    // =====================  QUADRATURE BLOCKS  =============================
    __shared__ float4     sh_qd[64];   // {q2_a, d2_a, q2_b, d2_b} per pair
    __shared__ ulonglong2 sh_pr[64];   // {pg packed, rho packed}  per pair
    const int blk = blockIdx.x;
    const int b   = blk >> 5;          // batch (32 blocks per batch)
    const int r   = blk & 31;          // pp*4 + q  == chunk index c
    const int pp  = r >> 2;            // pole pair 0..7
    const int q   = r & 3;             // node quarter

    {   // per-node precompute: all 128 threads (2 poles x 64 nodes)
        const int sel = t >> 6;        // pole within the pair
        const int tn  = t & 63;        // node within the quarter
        const int bp  = b * 16 + pp * 2 + sel;
        const int n   = q * 64 + tn;

        float eps = pre[bp];
        float gam = -pim[bp];
        float a   = rre[bp];
        float br  = rim[bp];
        float phi = tab.phi[n];
        float wq  = tab.wgt[n];

        float omega = fmaf(gam, phi, eps);
        float s     = fabsf(omega);
        float q2 = -omega * LOG2E_F;
        float d2 = 10.0f * fminf(omega, 0.0f) * LOG2E_F;
        float gfac = 1.0f / (1.0f + fexp2(-10.0f * LOG2E_F * s));
        float pg = 0.5f * fmaf(-br, phi, a) * wq * gfac;
        // clamp keeps rho finite; when active, the thread's starting
        // exponential has already flushed to 0 -> no corruption possible
        float rho = fexp2(fminf(q2 * (float)STEP_D, 80.0f));

        const int pr = sel * 32 + (tn >> 1), k = tn & 1;  // pair / half
        float* qd = (float*)&sh_qd[pr];
        qd[2 * k]     = q2;
        qd[2 * k + 1] = d2;
        float* ppk = (float*)&sh_pr[pr];
        ppk[k]     = pg;                       // pg packed lo/hi
        ppk[2 + k] = rho;                      // rho packed lo/hi
    }
    __syncthreads();

    if (t >= 125) return;              // 125 threads * 8 taus = 1000
    const int l0 = 8 * t;
    const float tau0 = (float)((double)l0 * STEP_D);

    unsigned long long A0 = 0, A1 = 0, A2 = 0, A3 = 0,
                       A4 = 0, A5 = 0, A6 = 0, A7 = 0;
    #pragma unroll 4
    for (int p = 0; p < 64; ++p) {     // 64 pairs = 2 poles x 64 nodes
        float4     qd = sh_qd[p];      // broadcast LDS.128
        ulonglong2 pr = sh_pr[p];      // broadcast LDS.128
        float e0 = fexp2(fmaf(qd.x, tau0, qd.y));
        float e1 = fexp2(fmaf(qd.z, tau0, qd.w));
        unsigned long long E = pk2(e0, e1);
        A0 = fma2(pr.x, E, A0);  E = mul2(E, pr.y);
        A1 = fma2(pr.x, E, A1);  E = mul2(E, pr.y);
        A2 = fma2(pr.x, E, A2);  E = mul2(E, pr.y);
        A3 = fma2(pr.x, E, A3);  E = mul2(E, pr.y);
        A4 = fma2(pr.x, E, A4);  E = mul2(E, pr.y);
        A5 = fma2(pr.x, E, A5);  E = mul2(E, pr.y);
        A6 = fma2(pr.x, E, A6);  E = mul2(E, pr.y);
        A7 = fma2(pr.x, E, A7);
    }

    float lo, hi, r0, r1, r2, r3, r4, r5, r6, r7;
    unpk2(lo, hi, A0); r0 = lo + hi;
    unpk2(lo, hi, A1); r1 = lo + hi;
    unpk2(lo, hi, A2); r2 = lo + hi;
    unpk2(lo, hi, A3); r3 = lo + hi;
    unpk2(lo, hi, A4); r4 = lo + hi;
    unpk2(lo, hi, A5); r5 = lo + hi;
    unpk2(lo, hi, A6); r6 = lo + hi;
    unpk2(lo, hi, A7); r7 = lo + hi;

    // transposed scatter: two STG.128, 512B stride between adjacent threads
    const size_t base = ((size_t)b * 250 + 2 * t) * 32 + r;
    g_partialT[base]      = make_float4(r0, r1, r2, r3);
    g_partialT[base + 32] = make_float4(r4, r5, r6, r7);
}

// ---------------------------------------------------------------------------
// Reduce kernel (grid 125 x 256): 8 threads per (b,g) tau-group.
// Thread sub s sums chunks {k*8+s}, k=0..3: per warp-instruction the 32 lane
// addresses form 4 contiguous 128B segments -> fully coalesced, 4 independent
// LDG.128 per thread, 2 MB total (half of R16 -> tests size-proportionality).
// 3-round shfl_xor butterfly (fixed order -> deterministic); lane sub==0
// stores out[b][4g..4g+3], skipping out[b][0] (owned by the G0 blocks).
// ---------------------------------------------------------------------------
__global__ void __launch_bounds__(256) reduce_kernel(float* __restrict__ out)
{
    const int tid = blockIdx.x * 256 + threadIdx.x;   // 0..31999
    const int gid = tid >> 3;                         // (b,g) group, 0..3999
    const int sub = tid & 7;                          // 8-way chunk split
    const int b   = gid / 250;
    const int g   = gid - 250 * b;

    const float4* __restrict__ src = &g_partialT[(size_t)gid * 32];
    float4 s = make_float4(0.f, 0.f, 0.f, 0.f);
    #pragma unroll
    for (int k = 0; k < 4; ++k) {                     // 4 coalesced loads
        float4 v = src[k * 8 + sub];
        s.x += v.x; s.y += v.y; s.z += v.z; s.w += v.w;
    }
    // 3-round butterfly within the 8-lane octet; fixed order -> deterministic
    #pragma unroll
    for (int m = 4; m > 0; m >>= 1) {
        s.x += __shfl_xor_sync(0xffffffffu, s.x, m);
        s.y += __shfl_xor_sync(0xffffffffu, s.y, m);
        s.z += __shfl_xor_sync(0xffffffffu, s.z, m);
        s.w += __shfl_xor_sync(0xffffffffu, s.w, m);
    }

    if (sub == 0) {
        float* dst = out + (size_t)b * LTAU + 4 * g;
        if (g == 0) { dst[1] = s.y; dst[2] = s.z; dst[3] = s.w; }
        else        { *(float4*)dst = s; }
    }
}

// ---------------------------------------------------------------------------
// Host: Gauss-Legendre nodes/weights (double Newton, fixed iteration count ->
// deterministic).  Runs at capture/correctness time only; values are baked
// into the graph as kernel parameters.  No device allocation, no stream ops.
// ---------------------------------------------------------------------------
static void host_leggauss(GLTab* tab)
{
    const int n = N_NODES;
    for (int i = 0; i < n; ++i) {
        double z = cos(PI_D * ((double)i + 0.75) / ((double)n + 0.5));
        double pp = 1.0;
        for (int it = 0; it < 6; ++it) {          // fixed count: deterministic
            double p1 = z, p2 = 1.0;
            for (int j = 1; j < n; ++j) {
                double p0 = ((2.0 * j + 1.0) * z * p1 - (double)j * p2)
                            / ((double)j + 1.0);
                p2 = p1; p1 = p0;
            }
            pp = (double)n * (z * p1 - p2) / (z * z - 1.0);
            z -= p1 / pp;
        }
        tab->phi[i] = (float)tan(1.5707963267948966 * z);
        tab->wgt[i] = (float)(2.0 / ((1.0 - z * z) * pp * pp));
    }
}

// ---------------------------------------------------------------------------
// Launch
// ---------------------------------------------------------------------------
extern "C" void kernel_launch(void* const* d_in, const int* in_sizes, int n_in,
                              void* d_out, int out_size)
{
    const float* pre = (const float*)d_in[0];  // poles_re    [16,16]
    const float* pim = (const float*)d_in[1];  // poles_im    [16,16]
    const float* rre = (const float*)d_in[2];  // residues_re [16,16]
    const float* rim = (const float*)d_in[3];  // residues_im [16,16]
    float* out = (float*)d_out;                // [16,1000] float32

    GLTab tab;                                 // recomputed every call (no caching)
    host_leggauss(&tab);

    quad_g0_kernel<<<512 + BATCH, 128>>>(tab, pre, pim, rre, rim, out);
    reduce_kernel<<<125, 256>>>(out);
}